// round 1
// baseline (speedup 1.0000x reference)
#include <cuda_runtime.h>
#include <cstdint>

// Layout after transpose: g_buf[n][plane][frame], plane 0 = x, plane 1 = y,
// 64 frames contiguous. Row stride = 128 floats = 512 bytes.
#define MAX_N 100000
__device__ __align__(256) float g_buf[(size_t)MAX_N * 128];
__device__ int g_is64;

// ---------------- f32x2 / sqrt.approx helpers ----------------
__device__ __forceinline__ unsigned long long fma2(unsigned long long a,
                                                   unsigned long long b,
                                                   unsigned long long c) {
    unsigned long long r;
    asm("fma.rn.f32x2 %0, %1, %2, %3;" : "=l"(r) : "l"(a), "l"(b), "l"(c));
    return r;
}
__device__ __forceinline__ unsigned long long mul2(unsigned long long a,
                                                   unsigned long long b) {
    unsigned long long r;
    asm("mul.rn.f32x2 %0, %1, %2;" : "=l"(r) : "l"(a), "l"(b));
    return r;
}
__device__ __forceinline__ void upk(unsigned long long v, float& a, float& b) {
    asm("mov.b64 {%0, %1}, %2;" : "=f"(a), "=f"(b) : "l"(v));
}
__device__ __forceinline__ unsigned long long pk(float a, float b) {
    unsigned long long r;
    asm("mov.b64 %0, {%1, %2};" : "=l"(r) : "f"(a), "f"(b));
    return r;
}
__device__ __forceinline__ float sqapx(float x) {
    float r;
    asm("sqrt.approx.f32 %0, %1;" : "=f"(r) : "f"(x));
    return r;
}

// ---------------- Kernel 0: dtype detect + output zero-init ----------------
// skeleton indices are in [0, 100000). If stored as little-endian int64, every
// odd 32-bit word is 0. 64 consecutive zero odd-words from random int32
// indices has ~0 probability.
__global__ void detect_kernel(const unsigned* __restrict__ skel, float* out) {
    if (threadIdx.x == 0) {
        int all0 = 1;
        for (int i = 0; i < 64; ++i) all0 &= (skel[2 * i + 1] == 0u);
        g_is64 = all0;
        out[0] = 0.0f;
    }
}

// ---------------- Kernel 1: transpose [64, N] float2 -> [N][2][64] float ----
__global__ void transpose_kernel(const float2* __restrict__ in, int N) {
    __shared__ float2 tile[64][33];
    int n0 = blockIdx.x * 32;
    int tx = threadIdx.x & 31;
    int ty = threadIdx.x >> 5;
    int c = n0 + tx;
    if (c < N) {
#pragma unroll
        for (int i = 0; i < 8; ++i) {
            int b = ty + i * 8;  // frame index 0..63
            tile[b][tx] = in[(size_t)b * N + c];
        }
    }
    __syncthreads();
#pragma unroll
    for (int k = 0; k < 8; ++k) {
        int l = threadIdx.x + k * 256;   // linear over (c,b): l = c*64 + b
        int b = l & 63;
        int cc = l >> 6;
        int n = n0 + cc;
        if (n < N) {
            float2 v = tile[b][cc];
            g_buf[(size_t)n * 128 + b] = v.x;        // x plane
            g_buf[(size_t)n * 128 + 64 + b] = v.y;   // y plane
        }
    }
}

// ---------------- Kernel 2: main loss ----------------
// Warp = 2 edges (half-warp each). Lane handles 4 frames: one ulonglong2
// (16B = 4 floats = 2 f32x2) per plane per endpoint. All math packed f32x2;
// sqrt via single-MUFU sqrt.approx.
__global__ void __launch_bounds__(256) loss_kernel(const void* __restrict__ skel_raw,
                                                   const float* __restrict__ init_len,
                                                   float* out, int E, float invE) {
    const unsigned long long NEG1 = 0xBF800000BF800000ULL;  // (-1.f, -1.f)
    int lane = threadIdx.x & 31;
    int half = lane >> 4;
    int fl = lane & 15;
    int warp = (blockIdx.x * blockDim.x + threadIdx.x) >> 5;
    int nwarps = (gridDim.x * blockDim.x) >> 5;
    int P = E >> 1;
    bool is64 = (g_is64 != 0);
    const char* tb = (const char*)g_buf + (size_t)fl * 16;

    unsigned long long accLo = 0ull, accHi = 0ull;  // (+0.f, +0.f) packed

    for (int p = warp; p < P; p += nwarps) {
        int e = 2 * p + half;
        int s0, s1;
        if (is64) {
            const long long* s = (const long long*)skel_raw;
            s0 = (int)s[2 * e];
            s1 = (int)s[2 * e + 1];
        } else {
            int2 s = ((const int2*)skel_raw)[e];
            s0 = s.x;
            s1 = s.y;
        }
        float c = init_len[e];

        const char* p0 = tb + (size_t)s0 * 512;
        const char* p1 = tb + (size_t)s1 * 512;
        ulonglong2 ax = *(const ulonglong2*)(p0);         // x of frames 4fl..4fl+3, endpoint 0
        ulonglong2 ay = *(const ulonglong2*)(p0 + 256);   // y
        ulonglong2 bx = *(const ulonglong2*)(p1);
        ulonglong2 by = *(const ulonglong2*)(p1 + 256);

        unsigned long long dxl = fma2(bx.x, NEG1, ax.x);
        unsigned long long dxh = fma2(bx.y, NEG1, ax.y);
        unsigned long long dyl = fma2(by.x, NEG1, ay.x);
        unsigned long long dyh = fma2(by.y, NEG1, ay.y);
        unsigned long long tl = fma2(dyl, dyl, mul2(dxl, dxl));
        unsigned long long th = fma2(dyh, dyh, mul2(dxh, dxh));

        float t0, t1, t2, t3;
        upk(tl, t0, t1);
        upk(th, t2, t3);
        unsigned long long ll = pk(sqapx(t0), sqapx(t1));
        unsigned long long lh = pk(sqapx(t2), sqapx(t3));
        unsigned long long cc = pk(c, c);
        unsigned long long dl = fma2(cc, NEG1, ll);
        unsigned long long dh = fma2(cc, NEG1, lh);
        accLo = fma2(dl, dl, accLo);
        accHi = fma2(dh, dh, accHi);
    }

    float a0, a1, a2, a3;
    upk(accLo, a0, a1);
    upk(accHi, a2, a3);
    float s = (a0 + a1) + (a2 + a3);
#pragma unroll
    for (int off = 16; off; off >>= 1)
        s += __shfl_down_sync(0xffffffffu, s, off);
    if (lane == 0) atomicAdd(out, s * invE);
}

extern "C" void kernel_launch(void* const* d_in, const int* in_sizes, int n_in,
                              void* d_out, int out_size) {
    const float2* pts = (const float2*)d_in[0];
    const void* skel = d_in[1];
    const float* initl = (const float*)d_in[2];
    float* out = (float*)d_out;

    int N = in_sizes[0] / 128;  // B=64 frames, 2 coords
    int E = in_sizes[2];

    detect_kernel<<<1, 32>>>((const unsigned*)skel, out);
    transpose_kernel<<<(N + 31) / 32, 256>>>(pts, N);
    loss_kernel<<<592, 256>>>(skel, initl, out, E, 1.0f / (float)E);
}

// round 3
// speedup vs baseline: 1.4195x; 1.4195x over previous
#include <cuda_runtime.h>
#include <cuda_fp16.h>
#include <cstdint>

// Layout after transpose: g_buf[n][plane][frame] in HALF precision.
// plane 0 = x, plane 1 = y, 64 frames contiguous (2B each).
// Per point: 2 planes * 64 frames * 2B = 256 bytes. Plane row = 128B.
#define MAX_N 100000
__device__ __align__(256) __half2 g_buf[(size_t)MAX_N * 64];
__device__ int g_is64;

// ---------------- f32x2 / sqrt.approx helpers ----------------
__device__ __forceinline__ unsigned long long fma2(unsigned long long a,
                                                   unsigned long long b,
                                                   unsigned long long c) {
    unsigned long long r;
    asm("fma.rn.f32x2 %0, %1, %2, %3;" : "=l"(r) : "l"(a), "l"(b), "l"(c));
    return r;
}
__device__ __forceinline__ unsigned long long mul2(unsigned long long a,
                                                   unsigned long long b) {
    unsigned long long r;
    asm("mul.rn.f32x2 %0, %1, %2;" : "=l"(r) : "l"(a), "l"(b));
    return r;
}
__device__ __forceinline__ void upk(unsigned long long v, float& a, float& b) {
    asm("mov.b64 {%0, %1}, %2;" : "=f"(a), "=f"(b) : "l"(v));
}
__device__ __forceinline__ unsigned long long pk(float a, float b) {
    unsigned long long r;
    asm("mov.b64 %0, {%1, %2};" : "=l"(r) : "f"(a), "f"(b));
    return r;
}
__device__ __forceinline__ unsigned long long pk2(float2 v) { return pk(v.x, v.y); }
__device__ __forceinline__ float sqapx(float x) {
    float r;
    asm("sqrt.approx.f32 %0, %1;" : "=f"(r) : "f"(x));
    return r;
}

// ---------------- Kernel 1: transpose [64, N] float2 -> half [N][2][64] ----
// Block 0 additionally: detect skeleton dtype (int64 vs int32) via parallel
// ballot over the first 64 odd 32-bit words, and zero the output scalar.
__global__ void __launch_bounds__(256) transpose_kernel(
    const float2* __restrict__ in, const unsigned* __restrict__ skel_raw,
    float* out, int N) {
    if (blockIdx.x == 0 && threadIdx.x < 32) {
        // indices < 100000 => if stored int64 (LE), all odd words are zero.
        unsigned v = skel_raw[2 * threadIdx.x + 1] | skel_raw[2 * (threadIdx.x + 32) + 1];
        unsigned b = __ballot_sync(0xffffffffu, v == 0u);
        if (threadIdx.x == 0) {
            g_is64 = (b == 0xffffffffu);
            out[0] = 0.0f;
        }
    }

    __shared__ float2 tile[64][33];
    int n0 = blockIdx.x * 32;
    int tx = threadIdx.x & 31;
    int ty = threadIdx.x >> 5;
    int c = n0 + tx;
    if (c < N) {
#pragma unroll
        for (int i = 0; i < 8; ++i) {
            int b = ty + i * 8;  // frame index 0..63
            tile[b][tx] = in[(size_t)b * N + c];
        }
    }
    __syncthreads();
    // 32 points * 32 frame-pairs = 1024 items; 256 threads * 4 iters.
#pragma unroll
    for (int k = 0; k < 4; ++k) {
        int l = threadIdx.x + k * 256;
        int bp = l & 31;      // frame pair: frames 2bp, 2bp+1
        int cc = l >> 5;      // point within block
        int n = n0 + cc;
        if (n < N) {
            float2 v0 = tile[2 * bp][cc];
            float2 v1 = tile[2 * bp + 1][cc];
            g_buf[(size_t)n * 64 + bp]      = __floats2half2_rn(v0.x, v1.x);  // x plane
            g_buf[(size_t)n * 64 + 32 + bp] = __floats2half2_rn(v0.y, v1.y);  // y plane
        }
    }
}

// ---------------- Kernel 2: main loss ----------------
// Warp = 4 edges (8 lanes each). Lane handles 8 frames: one uint4 (16B =
// 8 halves) per plane per endpoint. Convert to f32 on load; packed f32x2
// math; sqrt via single-MUFU sqrt.approx.
__global__ void __launch_bounds__(256) loss_kernel(const void* __restrict__ skel_raw,
                                                   const float* __restrict__ init_len,
                                                   float* out, int E, float invE) {
    const unsigned long long NEG1 = 0xBF800000BF800000ULL;  // (-1.f, -1.f)
    int lane = threadIdx.x & 31;
    int quarter = lane >> 3;   // which of 4 edges in warp
    int el = lane & 7;         // lane within edge: frames 8*el .. 8*el+7
    int warp = (blockIdx.x * blockDim.x + threadIdx.x) >> 5;
    int nwarps = (gridDim.x * blockDim.x) >> 5;
    int P = (E + 3) >> 2;
    bool is64 = (g_is64 != 0);
    const char* tb = (const char*)g_buf + (size_t)el * 16;

    unsigned long long acc = 0ull;

#pragma unroll 2
    for (int p = warp; p < P; p += nwarps) {
        int e = 4 * p + quarter;
        if (e >= E) break;
        int s0, s1;
        if (is64) {
            const long long* s = (const long long*)skel_raw;
            s0 = (int)s[2 * e];
            s1 = (int)s[2 * e + 1];
        } else {
            int2 s = ((const int2*)skel_raw)[e];
            s0 = s.x;
            s1 = s.y;
        }
        float c = init_len[e];
        unsigned long long cc2 = pk(c, c);

        const char* p0 = tb + (size_t)s0 * 256;
        const char* p1 = tb + (size_t)s1 * 256;
        uint4 ax = *(const uint4*)(p0);          // x halves, endpoint 0
        uint4 ay = *(const uint4*)(p0 + 128);    // y halves
        uint4 bx = *(const uint4*)(p1);
        uint4 by = *(const uint4*)(p1 + 128);

        const unsigned* axw = (const unsigned*)&ax;
        const unsigned* ayw = (const unsigned*)&ay;
        const unsigned* bxw = (const unsigned*)&bx;
        const unsigned* byw = (const unsigned*)&by;

#pragma unroll
        for (int i = 0; i < 4; ++i) {
            unsigned long long AX = pk2(__half22float2(*(const __half2*)&axw[i]));
            unsigned long long AY = pk2(__half22float2(*(const __half2*)&ayw[i]));
            unsigned long long BX = pk2(__half22float2(*(const __half2*)&bxw[i]));
            unsigned long long BY = pk2(__half22float2(*(const __half2*)&byw[i]));
            unsigned long long dx = fma2(BX, NEG1, AX);
            unsigned long long dy = fma2(BY, NEG1, AY);
            unsigned long long t = fma2(dy, dy, mul2(dx, dx));
            float t0, t1;
            upk(t, t0, t1);
            unsigned long long len = pk(sqapx(t0), sqapx(t1));
            unsigned long long d = fma2(cc2, NEG1, len);
            acc = fma2(d, d, acc);
        }
    }

    float a0, a1;
    upk(acc, a0, a1);
    float s = a0 + a1;
#pragma unroll
    for (int off = 16; off; off >>= 1)
        s += __shfl_down_sync(0xffffffffu, s, off);
    if (lane == 0) atomicAdd(out, s * invE);
}

extern "C" void kernel_launch(void* const* d_in, const int* in_sizes, int n_in,
                              void* d_out, int out_size) {
    const float2* pts = (const float2*)d_in[0];
    const void* skel = d_in[1];
    const float* initl = (const float*)d_in[2];
    float* out = (float*)d_out;

    int N = in_sizes[0] / 128;  // B=64 frames, 2 coords
    int E = in_sizes[2];

    transpose_kernel<<<(N + 31) / 32, 256>>>(pts, (const unsigned*)skel, out, N);
    loss_kernel<<<592, 256>>>(skel, initl, out, E, 1.0f / (float)E);
}

// round 4
// speedup vs baseline: 1.6531x; 1.1645x over previous
#include <cuda_runtime.h>
#include <cuda_fp16.h>
#include <cstdint>

// Layout after transpose: g_buf[n][plane][frame] in HALF precision.
// plane 0 = x, plane 1 = y, 64 frames contiguous (2B each).
// Per point: 2 planes * 64 frames * 2B = 256 bytes. Plane row = 128B.
#define MAX_N 100000
__device__ __align__(256) __half2 g_buf[(size_t)MAX_N * 64];
__device__ int g_is64;

// ---------------- f32x2 / sqrt.approx helpers ----------------
__device__ __forceinline__ unsigned long long fma2(unsigned long long a,
                                                   unsigned long long b,
                                                   unsigned long long c) {
    unsigned long long r;
    asm("fma.rn.f32x2 %0, %1, %2, %3;" : "=l"(r) : "l"(a), "l"(b), "l"(c));
    return r;
}
__device__ __forceinline__ unsigned long long mul2(unsigned long long a,
                                                   unsigned long long b) {
    unsigned long long r;
    asm("mul.rn.f32x2 %0, %1, %2;" : "=l"(r) : "l"(a), "l"(b));
    return r;
}
__device__ __forceinline__ void upk(unsigned long long v, float& a, float& b) {
    asm("mov.b64 {%0, %1}, %2;" : "=f"(a), "=f"(b) : "l"(v));
}
__device__ __forceinline__ unsigned long long pk(float a, float b) {
    unsigned long long r;
    asm("mov.b64 %0, {%1, %2};" : "=l"(r) : "f"(a), "f"(b));
    return r;
}
__device__ __forceinline__ unsigned long long pk2(float2 v) { return pk(v.x, v.y); }
__device__ __forceinline__ float sqapx(float x) {
    float r;
    asm("sqrt.approx.f32 %0, %1;" : "=f"(r) : "f"(x));
    return r;
}

// ---------------- Kernel 1: transpose [64, N] float2 -> half [N][2][64] ----
// Block 0 additionally: detect skeleton dtype (int64 vs int32) via parallel
// ballot over the first 64 odd 32-bit words, and zero the output scalar.
__global__ void __launch_bounds__(256) transpose_kernel(
    const float2* __restrict__ in, const unsigned* __restrict__ skel_raw,
    float* out, int N) {
    if (blockIdx.x == 0 && threadIdx.x < 32) {
        // indices < 100000 => if stored int64 (LE), all odd words are zero.
        unsigned v = skel_raw[2 * threadIdx.x + 1] | skel_raw[2 * (threadIdx.x + 32) + 1];
        unsigned b = __ballot_sync(0xffffffffu, v == 0u);
        if (threadIdx.x == 0) {
            g_is64 = (b == 0xffffffffu);
            out[0] = 0.0f;
        }
    }

    __shared__ float2 tile[64][33];
    int n0 = blockIdx.x * 32;
    int tx = threadIdx.x & 31;
    int ty = threadIdx.x >> 5;
    int c = n0 + tx;
    if (c < N) {
#pragma unroll
        for (int i = 0; i < 8; ++i) {
            int b = ty + i * 8;  // frame index 0..63
            tile[b][tx] = in[(size_t)b * N + c];
        }
    }
    __syncthreads();
    // 32 points * 32 frame-pairs = 1024 items; 256 threads * 4 iters.
#pragma unroll
    for (int k = 0; k < 4; ++k) {
        int l = threadIdx.x + k * 256;
        int bp = l & 31;      // frame pair: frames 2bp, 2bp+1
        int cc = l >> 5;      // point within block
        int n = n0 + cc;
        if (n < N) {
            float2 v0 = tile[2 * bp][cc];
            float2 v1 = tile[2 * bp + 1][cc];
            g_buf[(size_t)n * 64 + bp]      = __floats2half2_rn(v0.x, v1.x);  // x plane
            g_buf[(size_t)n * 64 + 32 + bp] = __floats2half2_rn(v0.y, v1.y);  // y plane
        }
    }
}

// ---------------- Kernel 2: main loss ----------------
// Warp = 4 edges (8 lanes each). Lane handles 8 frames: one uint4 (16B =
// 8 halves) per plane per endpoint. Index/init_len loads for the NEXT
// iteration are prefetched before the current gathers so the idx->gather
// chain is off the critical path. Block-level reduction before one atomic.
__global__ void __launch_bounds__(256, 6) loss_kernel(
    const void* __restrict__ skel_raw, const float* __restrict__ init_len,
    float* out, int E, float invE) {
    const unsigned long long NEG1 = 0xBF800000BF800000ULL;  // (-1.f, -1.f)
    int lane = threadIdx.x & 31;
    int quarter = lane >> 3;   // which of 4 edges in warp
    int el = lane & 7;         // lane within edge: frames 8*el .. 8*el+7
    int warp = (blockIdx.x * blockDim.x + threadIdx.x) >> 5;
    int nwarps = (gridDim.x * blockDim.x) >> 5;
    int P = (E + 3) >> 2;
    bool is64 = (g_is64 != 0);
    const char* tb = (const char*)g_buf + (size_t)el * 16;

    unsigned long long acc = 0ull;

    // ---- prologue: load indices for first assigned quad ----
    int p = warp;
    int s0 = 0, s1 = 0;
    float c = 0.0f;
    bool valid = false;
    if (p < P) {
        int e = 4 * p + quarter;
        valid = (e < E);
        if (valid) {
            if (is64) {
                longlong2 s = ((const longlong2*)skel_raw)[e];
                s0 = (int)s.x;
                s1 = (int)s.y;
            } else {
                int2 s = ((const int2*)skel_raw)[e];
                s0 = s.x;
                s1 = s.y;
            }
            c = init_len[e];
        }
    }

    while (p < P) {
        // snapshot current
        int cs0 = s0, cs1 = s1;
        float cc = c;
        bool cvalid = valid;

        // prefetch next iteration's indices (overlaps with gathers below)
        p += nwarps;
        valid = false;
        if (p < P) {
            int e = 4 * p + quarter;
            valid = (e < E);
            if (valid) {
                if (is64) {
                    longlong2 s = ((const longlong2*)skel_raw)[e];
                    s0 = (int)s.x;
                    s1 = (int)s.y;
                } else {
                    int2 s = ((const int2*)skel_raw)[e];
                    s0 = s.x;
                    s1 = s.y;
                }
                c = init_len[e];
            }
        }

        if (cvalid) {
            const char* p0 = tb + (size_t)cs0 * 256;
            const char* p1 = tb + (size_t)cs1 * 256;
            uint4 ax = *(const uint4*)(p0);          // x halves, endpoint 0
            uint4 ay = *(const uint4*)(p0 + 128);    // y halves
            uint4 bx = *(const uint4*)(p1);
            uint4 by = *(const uint4*)(p1 + 128);

            unsigned long long cc2 = pk(cc, cc);
            const unsigned* axw = (const unsigned*)&ax;
            const unsigned* ayw = (const unsigned*)&ay;
            const unsigned* bxw = (const unsigned*)&bx;
            const unsigned* byw = (const unsigned*)&by;

#pragma unroll
            for (int i = 0; i < 4; ++i) {
                unsigned long long AX = pk2(__half22float2(*(const __half2*)&axw[i]));
                unsigned long long AY = pk2(__half22float2(*(const __half2*)&ayw[i]));
                unsigned long long BX = pk2(__half22float2(*(const __half2*)&bxw[i]));
                unsigned long long BY = pk2(__half22float2(*(const __half2*)&byw[i]));
                unsigned long long dx = fma2(BX, NEG1, AX);
                unsigned long long dy = fma2(BY, NEG1, AY);
                unsigned long long t = fma2(dy, dy, mul2(dx, dx));
                float t0, t1;
                upk(t, t0, t1);
                unsigned long long len = pk(sqapx(t0), sqapx(t1));
                unsigned long long d = fma2(cc2, NEG1, len);
                acc = fma2(d, d, acc);
            }
        }
    }

    float a0, a1;
    upk(acc, a0, a1);
    float s = a0 + a1;
#pragma unroll
    for (int off = 16; off; off >>= 1)
        s += __shfl_down_sync(0xffffffffu, s, off);

    __shared__ float warp_sums[8];
    if (lane == 0) warp_sums[threadIdx.x >> 5] = s;
    __syncthreads();
    if (threadIdx.x < 8) {
        float v = warp_sums[threadIdx.x];
#pragma unroll
        for (int off = 4; off; off >>= 1)
            v += __shfl_down_sync(0xffu, v, off);
        if (threadIdx.x == 0) atomicAdd(out, v * invE);
    }
}

extern "C" void kernel_launch(void* const* d_in, const int* in_sizes, int n_in,
                              void* d_out, int out_size) {
    const float2* pts = (const float2*)d_in[0];
    const void* skel = d_in[1];
    const float* initl = (const float*)d_in[2];
    float* out = (float*)d_out;

    int N = in_sizes[0] / 128;  // B=64 frames, 2 coords
    int E = in_sizes[2];

    transpose_kernel<<<(N + 31) / 32, 256>>>(pts, (const unsigned*)skel, out, N);
    loss_kernel<<<888, 256>>>(skel, initl, out, E, 1.0f / (float)E);
}

// round 5
// speedup vs baseline: 1.7827x; 1.0784x over previous
#include <cuda_runtime.h>
#include <cuda_fp16.h>
#include <cstdint>

// Layout after transpose: g_buf[n][plane][frame] in HALF precision.
// plane 0 = x, plane 1 = y, 64 frames contiguous (2B each).
// Per point: 2 planes * 64 frames * 2B = 256 bytes. Plane row = 128B.
#define MAX_N 100000
__device__ __align__(256) __half2 g_buf[(size_t)MAX_N * 64];
__device__ int g_is64;

// ---------------- f32x2 / sqrt.approx helpers ----------------
__device__ __forceinline__ unsigned long long fma2(unsigned long long a,
                                                   unsigned long long b,
                                                   unsigned long long c) {
    unsigned long long r;
    asm("fma.rn.f32x2 %0, %1, %2, %3;" : "=l"(r) : "l"(a), "l"(b), "l"(c));
    return r;
}
__device__ __forceinline__ void upk(unsigned long long v, float& a, float& b) {
    asm("mov.b64 {%0, %1}, %2;" : "=f"(a), "=f"(b) : "l"(v));
}
__device__ __forceinline__ unsigned long long pk(float a, float b) {
    unsigned long long r;
    asm("mov.b64 %0, {%1, %2};" : "=l"(r) : "f"(a), "f"(b));
    return r;
}
__device__ __forceinline__ float sqapx(float x) {
    float r;
    asm("sqrt.approx.f32 %0, %1;" : "=f"(r) : "f"(x));
    return r;
}

// ---------------- Kernel 1: transpose [64, N] float2 -> half [N][2][64] ----
// Block 0 additionally: detect skeleton dtype (int64 vs int32) via parallel
// ballot over the first 64 odd 32-bit words, and zero the output scalar.
// Input reads use __ldcs (evict-first) so the 51MB stream does not evict
// the freshly written 25.6MB g_buf from L2.
__global__ void __launch_bounds__(256) transpose_kernel(
    const float2* __restrict__ in, const unsigned* __restrict__ skel_raw,
    float* out, int N) {
    if (blockIdx.x == 0 && threadIdx.x < 32) {
        unsigned v = skel_raw[2 * threadIdx.x + 1] | skel_raw[2 * (threadIdx.x + 32) + 1];
        unsigned b = __ballot_sync(0xffffffffu, v == 0u);
        if (threadIdx.x == 0) {
            g_is64 = (b == 0xffffffffu);
            out[0] = 0.0f;
        }
    }

    __shared__ float2 tile[64][33];
    int n0 = blockIdx.x * 32;
    int tx = threadIdx.x & 31;
    int ty = threadIdx.x >> 5;
    int c = n0 + tx;
    if (c < N) {
#pragma unroll
        for (int i = 0; i < 8; ++i) {
            int b = ty + i * 8;  // frame index 0..63
            tile[b][tx] = __ldcs(&in[(size_t)b * N + c]);
        }
    }
    __syncthreads();
#pragma unroll
    for (int k = 0; k < 4; ++k) {
        int l = threadIdx.x + k * 256;
        int bp = l & 31;      // frame pair: frames 2bp, 2bp+1
        int cc = l >> 5;      // point within block
        int n = n0 + cc;
        if (n < N) {
            float2 v0 = tile[2 * bp][cc];
            float2 v1 = tile[2 * bp + 1][cc];
            g_buf[(size_t)n * 64 + bp]      = __floats2half2_rn(v0.x, v1.x);  // x plane
            g_buf[(size_t)n * 64 + 32 + bp] = __floats2half2_rn(v0.y, v1.y);  // y plane
        }
    }
}

// ---------------- Kernel 2: main loss ----------------
// Warp = 4 edges (8 lanes each). Lane handles 8 frames via one uint4 (16B =
// 8 halves) per plane per endpoint. 2-deep software pipeline: while computing
// iteration p, gathers for p+1 are in flight and indices for p+2 are loading.
// Inner math in native half2 (HSUB2/HMUL2/HFMA2); f32 only from the sqrt on.
// Tail is branch-free: e >= E is clamped to s0=s1=0, c=0 => contributes 0.

struct Quad { int s0, s1; float c; };
struct Gather { uint4 ax, ay, bx, by; };

__device__ __forceinline__ Quad load_idx(const void* skel_raw,
                                         const float* init_len,
                                         int e, int E, bool is64) {
    Quad q;
    int ec = e < E ? e : (E - 1);
    if (is64) {
        longlong2 s = ((const longlong2*)skel_raw)[ec];
        q.s0 = (int)s.x;
        q.s1 = (int)s.y;
    } else {
        int2 s = ((const int2*)skel_raw)[ec];
        q.s0 = s.x;
        q.s1 = s.y;
    }
    q.c = init_len[ec];
    if (e >= E) { q.s0 = 0; q.s1 = 0; q.c = 0.0f; }
    return q;
}

__device__ __forceinline__ Gather issue_gather(const char* tb, Quad q) {
    Gather g;
    const char* p0 = tb + (size_t)q.s0 * 256;
    const char* p1 = tb + (size_t)q.s1 * 256;
    g.ax = *(const uint4*)(p0);
    g.ay = *(const uint4*)(p0 + 128);
    g.bx = *(const uint4*)(p1);
    g.by = *(const uint4*)(p1 + 128);
    return g;
}

__global__ void __launch_bounds__(256, 4) loss_kernel(
    const void* __restrict__ skel_raw, const float* __restrict__ init_len,
    float* out, int E, float invE) {
    const unsigned long long NEG1 = 0xBF800000BF800000ULL;  // (-1.f, -1.f)
    int lane = threadIdx.x & 31;
    int quarter = lane >> 3;   // which of 4 edges in warp
    int el = lane & 7;         // lane within edge: frames 8*el .. 8*el+7
    int warp = (blockIdx.x * blockDim.x + threadIdx.x) >> 5;
    int nwarps = (gridDim.x * blockDim.x) >> 5;
    int P = (E + 3) >> 2;
    bool is64 = (g_is64 != 0);
    const char* tb = (const char*)g_buf + (size_t)el * 16;

    unsigned long long acc = 0ull;

    // Pipeline prologue: indices for p and p+1; gathers for p.
    int p = warp;
    Quad qc = load_idx(skel_raw, init_len, 4 * p + quarter, E, is64);
    Gather gc = issue_gather(tb, qc);
    Quad qn = load_idx(skel_raw, init_len, 4 * (p + nwarps) + quarter, E, is64);

    for (; p < P; p += nwarps) {
        int pn2 = p + 2 * nwarps;
        // Issue next iteration's gathers (indices already resident).
        Gather gn = issue_gather(tb, qn);
        // Start loading indices two iterations ahead.
        Quad qf;
        bool have_f = (p + nwarps) < P;
        if (have_f)
            qf = load_idx(skel_raw, init_len, 4 * pn2 + quarter, E, is64);

        // Compute on current gathers (in flight since previous iteration).
        unsigned long long cc2 = pk(qc.c, qc.c);
        const __half2* axh = (const __half2*)&gc.ax;
        const __half2* ayh = (const __half2*)&gc.ay;
        const __half2* bxh = (const __half2*)&gc.bx;
        const __half2* byh = (const __half2*)&gc.by;
#pragma unroll
        for (int i = 0; i < 4; ++i) {
            __half2 dx = __hsub2(axh[i], bxh[i]);
            __half2 dy = __hsub2(ayh[i], byh[i]);
            __half2 t = __hfma2(dy, dy, __hmul2(dx, dx));
            float2 tf = __half22float2(t);
            unsigned long long len = pk(sqapx(tf.x), sqapx(tf.y));
            unsigned long long d = fma2(cc2, NEG1, len);
            acc = fma2(d, d, acc);
        }

        // Rotate pipeline.
        qc = qn;
        gc = gn;
        if (have_f) qn = qf;
    }

    float a0, a1;
    upk(acc, a0, a1);
    float s = a0 + a1;
#pragma unroll
    for (int off = 16; off; off >>= 1)
        s += __shfl_down_sync(0xffffffffu, s, off);

    __shared__ float warp_sums[8];
    if (lane == 0) warp_sums[threadIdx.x >> 5] = s;
    __syncthreads();
    if (threadIdx.x < 8) {
        float v = warp_sums[threadIdx.x];
#pragma unroll
        for (int off = 4; off; off >>= 1)
            v += __shfl_down_sync(0xffu, v, off);
        if (threadIdx.x == 0) atomicAdd(out, v * invE);
    }
}

extern "C" void kernel_launch(void* const* d_in, const int* in_sizes, int n_in,
                              void* d_out, int out_size) {
    const float2* pts = (const float2*)d_in[0];
    const void* skel = d_in[1];
    const float* initl = (const float*)d_in[2];
    float* out = (float*)d_out;

    int N = in_sizes[0] / 128;  // B=64 frames, 2 coords
    int E = in_sizes[2];

    transpose_kernel<<<(N + 31) / 32, 256>>>(pts, (const unsigned*)skel, out, N);
    loss_kernel<<<592, 256>>>(skel, initl, out, E, 1.0f / (float)E);
}